// round 12
// baseline (speedup 1.0000x reference)
#include <cuda_runtime.h>

// CCSDS-123 lossless predictor, [Z=224, Y=512, X=512].
// 2 bands x 4 rows per 512-thread block. Band z's center rows in smem serve as
// band z+1's prev-band rows, halving prev-band L2/LTS read traffic.
// All loads up front, one barrier, two flat compute+store phases.

#define ZB 224
#define YB 512
#define XB 512

static constexpr size_t PLANE = (size_t)ZB * YB * XB;   // 58,720,256

__device__ __forceinline__ void compute_store_row(
    const float* __restrict__ sc, const float* __restrict__ sn,
    const float* __restrict__ sp, float* __restrict__ out,
    int z, int y, int x0)
{
    float pr[4], rs[4], mp[4], rc[4];
#pragma unroll
    for (int i = 0; i < 4; ++i) {
        const int x = x0 + i;
        const float Cv  = sc[x];
        const float Wv  = (x > 0)      ? sc[x - 1] : 0.f;
        const float Nv  = sn[x];
        const float NWv = (x > 0)      ? sn[x - 1] : 0.f;
        const float NEv = (x < XB - 1) ? sn[x + 1] : 0.f;

        // neighbor-oriented local sum with edge cases
        float sigma;
        if (y == 0)           sigma = (x == 0) ? 0.f : 4.f * Wv;   // top row
        else if (x == 0)      sigma = 2.f * (Nv + NEv);            // left col
        else if (x == XB - 1) sigma = Wv + NWv + 2.f * Nv;         // right col
        else                  sigma = Wv + NWv + Nv + NEv;         // interior

        const float spred = sigma * 0.25f;
        const float pb    = sp[x];

        float p = (z == 0) ? spred : 0.5f * (spred + pb);
        if (y == 0 && x == 0) p = (z == 0) ? 0.f : pb;             // origin

        const float r  = Cv - p;                   // residual (== quantized)
        const float qv = rintf(r);                 // half-to-even, matches jnp.round
        const float m  = (qv >= 0.f) ? (2.f * qv) : (-2.f * qv - 1.f); // zigzag
        const float rec = fminf(fmaxf(p + r, -32768.f), 32767.f);  // clip

        pr[i] = p; rs[i] = r; mp[i] = m; rc[i] = rec;
    }

    const size_t off = ((size_t)z * YB + y) * XB + (size_t)x0;
    const float4 v_p = make_float4(pr[0], pr[1], pr[2], pr[3]);
    const float4 v_r = make_float4(rs[0], rs[1], rs[2], rs[3]);
    const float4 v_m = make_float4(mp[0], mp[1], mp[2], mp[3]);
    const float4 v_c = make_float4(rc[0], rc[1], rc[2], rc[3]);

    __stcs((float4*)(out + off),             v_p);  // predictions
    __stcs((float4*)(out + off + PLANE),     v_r);  // residuals
    __stcs((float4*)(out + off + 2 * PLANE), v_r);  // quantized residuals
    __stcs((float4*)(out + off + 3 * PLANE), v_m);  // mapped indices
    __stcs((float4*)(out + off + 4 * PLANE), v_c);  // sample representatives
    __stcs((float4*)(out + off + 5 * PLANE), v_c);  // reconstructed
}

__global__ __launch_bounds__(512, 4) void ccsds123_kernel(
    const float* __restrict__ img, float* __restrict__ out)
{
    const int b   = blockIdx.x;          // 112 zpairs * 128 yquads
    const int zp  = b >> 7;              // z pair index
    const int z   = zp * 2;
    const int y0  = (b & 127) << 2;      // row quad
    const int tid = threadIdx.x;

    __shared__ float SC0[4 * XB];  // band z   center rows y0..y0+3
    __shared__ float SC1[4 * XB];  // band z+1 center rows y0..y0+3
    __shared__ float SP [4 * XB];  // band z-1 rows y0..y0+3
    __shared__ float SN0[XB];      // band z   north row y0-1
    __shared__ float SN1[XB];      // band z+1 north row y0-1

    const float* base0 = img + ((size_t)z * YB + y0) * XB;         // band z
    const float* base1 = base0 + (size_t)YB * XB;                  // band z+1
    const float* pbase = base0 - (size_t)YB * XB;                  // band z-1

    // ── Stage everything (max MLP, no intermediate barriers) ──
    ((float4*)SC0)[tid] = ((const float4*)base0)[tid];
    ((float4*)SC1)[tid] = ((const float4*)base1)[tid];
    if (z > 0) {
        const float* p = (const float*)((const float4*)pbase + tid);
        float4 pv;
        pv.x = __ldcs(p + 0);
        pv.y = __ldcs(p + 1);
        pv.z = __ldcs(p + 2);
        pv.w = __ldcs(p + 3);
        ((float4*)SP)[tid] = pv;
    } else {
        ((float4*)SP)[tid] = make_float4(0.f, 0.f, 0.f, 0.f);
    }
    if (tid < 128) {
        ((float4*)SN0)[tid] = (y0 > 0) ? ((const float4*)(base0 - XB))[tid]
                                       : make_float4(0.f, 0.f, 0.f, 0.f);
    } else if (tid < 256) {
        const int t = tid - 128;
        ((float4*)SN1)[t] = (y0 > 0) ? ((const float4*)(base1 - XB))[t]
                                     : make_float4(0.f, 0.f, 0.f, 0.f);
    }
    __syncthreads();

    const int q  = tid >> 7;                 // which of the four rows
    const int t  = tid & 127;
    const int x0 = t * 4;
    const int y  = y0 + q;

    // Phase 1: band z (prev = SP)
    compute_store_row(SC0 + q * XB,
                      q ? (SC0 + (q - 1) * XB) : SN0,
                      SP + q * XB,
                      out, z, y, x0);

    // Phase 2: band z+1 (prev = SC0, already in smem)
    compute_store_row(SC1 + q * XB,
                      q ? (SC1 + (q - 1) * XB) : SN1,
                      SC0 + q * XB,
                      out, z + 1, y, x0);
}

extern "C" void kernel_launch(void* const* d_in, const int* in_sizes, int n_in,
                              void* d_out, int out_size)
{
    const float* img = (const float*)d_in[0];
    float* out = (float*)d_out;
    ccsds123_kernel<<<(ZB / 2) * (YB / 4), 512>>>(img, out);
}